// round 3
// baseline (speedup 1.0000x reference)
#include <cuda_runtime.h>
#include <math.h>

// Problem constants (fixed by setup_inputs)
#define B 4
#define H 256
#define W 256
#define NPTS 256
#define HW (H*W)
#define NSTEPS 50
#define STEPSZ 0.1f
#define ALPHA 0.01f
#define BETA 0.005f
#define DMAX 15.0f
#define EXTGRADFAC 10.0f
// filter: stdev=2 -> r=6 -> 13 taps

// ---------------- device scratch (static allocation: allowed) ----------------
__device__ float  g_ag [B*HW];     // conv_x(pred, g)
__device__ float  g_adg[B*HW];     // conv_x(pred, dg)
__device__ float  g_bg [B*HW];     // conv_x(|pred|, g)
__device__ float  g_bdg[B*HW];     // conv_x(|pred|, dg)
__device__ float2 g_gimg [B*HW];   // interleaved {fy,fx} per pixel
__device__ float2 g_gimgW[B*HW];
__device__ float4 g_nodes[B*NPTS]; // {y, x, w, pad}
__device__ float  g_part[1024];

__device__ __forceinline__ float sqrt_approx(float q) {
    float r;
    asm("sqrt.approx.f32 %0, %1;" : "=f"(r) : "f"(q));
    return r;   // exact 0 at q == 0
}

// Compute the 13-tap Gaussian / derivative-of-Gaussian filter into shared mem.
// Matches the numpy float32 recipe: g = exp(-x^2/8); g /= sum(g); dg = -x/4 * g.
__device__ __forceinline__ void make_filter(float* g, float* dg, int tid) {
    if (tid < 13) {
        float xv = (float)(tid - 6);
        g[tid] = expf(-xv * xv * 0.125f);
    }
    __syncthreads();
    if (tid == 0) {
        float s = 0.f;
        #pragma unroll
        for (int i = 0; i < 13; i++) s += g[i];
        #pragma unroll
        for (int i = 0; i < 13; i++) {
            g[i]  = g[i] / s;
            dg[i] = -(float)(i - 6) * 0.25f * g[i];
        }
    }
    __syncthreads();
}

// ---------------- pass 1: horizontal separable conv ----------------
// One block per image row (B*H blocks, 256 threads).
__global__ void conv_pass1(const float* __restrict__ pred) {
    __shared__ float g[13], dg[13];
    __shared__ float spd[W + 12], sab[W + 12];
    const int tid = threadIdx.x;
    const int row = blockIdx.x;          // b*H + y

    if (tid < 13) {
        float xv = (float)(tid - 6);
        g[tid] = expf(-xv * xv * 0.125f);
    }
    float v = pred[row * W + tid];
    spd[tid + 6] = v;
    sab[tid + 6] = fabsf(v);
    if (tid < 6) {
        spd[tid] = 0.f; sab[tid] = 0.f;
        spd[W + 6 + tid] = 0.f; sab[W + 6 + tid] = 0.f;
    }
    __syncthreads();
    if (tid == 0) {
        float s = 0.f;
        #pragma unroll
        for (int i = 0; i < 13; i++) s += g[i];
        #pragma unroll
        for (int i = 0; i < 13; i++) {
            g[i]  = g[i] / s;
            dg[i] = -(float)(i - 6) * 0.25f * g[i];
        }
    }
    __syncthreads();

    float ag = 0.f, adg = 0.f, bg = 0.f, bdg = 0.f;
    #pragma unroll
    for (int j = 0; j < 13; j++) {
        float p = spd[tid + j];
        float a = sab[tid + j];
        ag  = fmaf(p, g[j],  ag);
        adg = fmaf(p, dg[j], adg);
        bg  = fmaf(a, g[j],  bg);
        bdg = fmaf(a, dg[j], bdg);
    }
    const int o = row * W + tid;
    g_ag[o] = ag; g_adg[o] = adg; g_bg[o] = bg; g_bdg[o] = bdg;
}

// ---------------- pass 2: vertical separable conv + scale ----------------
// One block per image row (B*H blocks, 256 threads). Writes interleaved float2.
__global__ void conv_pass2() {
    __shared__ float g[13], dg[13];
    const int tid = threadIdx.x;
    const int row = blockIdx.x;          // b*H + y
    make_filter(g, dg, tid);

    const int b = row >> 8;
    const int y = row & 255;
    float o0 = 0.f, o1 = 0.f, o2 = 0.f, o3 = 0.f;
    #pragma unroll
    for (int i = 0; i < 13; i++) {
        int yy = y + i - 6;
        if (yy < 0 || yy >= H) continue;
        int idx = (b * H + yy) * W + tid;
        o0 = fmaf(g_ag [idx], dg[i], o0);   // fy channel of gimg
        o1 = fmaf(g_adg[idx], g[i],  o1);   // fx channel of gimg
        o2 = fmaf(g_bg [idx], dg[i], o2);   // fy channel of gimgW
        o3 = fmaf(g_bdg[idx], g[i],  o3);   // fx channel of gimgW
    }
    const int base = b * HW + y * W + tid;
    g_gimg [base] = make_float2(o0 * EXTGRADFAC, o1 * EXTGRADFAC);
    g_gimgW[base] = make_float2(o2 * EXTGRADFAC, o3 * EXTGRADFAC);
}

// ---------------- bilinear sampler over an interleaved float2 image --------
__device__ __forceinline__ void bilin2(const float2* __restrict__ img,
                                       float y, float x, float& r0, float& r1) {
    y = fminf(fmaxf(y, 0.f), 254.999f);   // H - 1.001
    x = fminf(fmaxf(x, 0.f), 254.999f);
    float fy = floorf(y), fx = floorf(x);
    int y0 = (int)fy, x0 = (int)fx;
    float ty = y - fy, tx = x - fx;
    float w00 = (1.f - ty) * (1.f - tx);
    float w01 = (1.f - ty) * tx;
    float w10 = ty * (1.f - tx);
    float w11 = ty * tx;
    int i = y0 * W + x0;
    float2 v00 = __ldg(img + i),     v01 = __ldg(img + i + 1);
    float2 v10 = __ldg(img + i + W), v11 = __ldg(img + i + W + 1);
    r0 = v00.x * w00 + v01.x * w01 + v10.x * w10 + v11.x * w11;
    r1 = v00.y * w00 + v01.y * w01 + v10.y * w10 + v11.y * w11;
}

// ---------------- snake optimization: 4 blocks, 256 threads ----------------
// Ping-pong buffers + direct 5-point d4 stencil: ONE barrier per step.
__global__ void snake(const float* __restrict__ node_pos,
                      const float* __restrict__ widths) {
    __shared__ float pyA[NPTS], pxA[NPTS], wdA[NPTS];
    __shared__ float pyB[NPTS], pxB[NPTS], wdB[NPTS];
    const int i = threadIdx.x;
    const int b = blockIdx.x;
    const float2* gi = g_gimg  + b * HW;
    const float2* gw = g_gimgW + b * HW;

    pyA[i] = node_pos[(b * NPTS + i) * 2 + 0];
    pxA[i] = node_pos[(b * NPTS + i) * 2 + 1];
    wdA[i] = widths[b * NPTS + i];
    __syncthreads();

    // clamped neighbor indices (edge replication, matching jnp concat stencil)
    const int im1 = (i == 0) ? 0 : i - 1;
    const int ip1 = (i == NPTS - 1) ? NPTS - 1 : i + 1;
    const int im2 = (i <= 1) ? 0 : i - 2;
    const int ip2 = (i >= NPTS - 2) ? NPTS - 1 : i + 2;
    // clamped neighbors *of* im1 / ip1 for the nested d2 evaluation
    const int im1m = (im1 == 0) ? 0 : im1 - 1;           // == im2
    const int im1p = (im1 == NPTS - 1) ? NPTS - 1 : im1 + 1;
    const int ip1m = (ip1 == 0) ? 0 : ip1 - 1;
    const int ip1p = (ip1 == NPTS - 1) ? NPTS - 1 : ip1 + 1;  // == ip2
    (void)im2; (void)ip2;

    float *py = pyA, *px = pxA, *wd = wdA;
    float *qy = pyB, *qx = pxB, *qw = wdB;

    for (int step = 0; step < NSTEPS; step++) {
        float y = py[i], x = px[i];
        float f0, f1;
        bilin2(gi, y, x, f0, f1);

        // d2 at i, im1, ip1 evaluated directly (exact nested-_d2 semantics)
        float d2y  = py[im1]  - 2.f * y       + py[ip1];
        float d2x  = px[im1]  - 2.f * x       + px[ip1];
        float d2ym = py[im1m] - 2.f * py[im1] + py[im1p];
        float d2xm = px[im1m] - 2.f * px[im1] + px[im1p];
        float d2yp = py[ip1m] - 2.f * py[ip1] + py[ip1p];
        float d2xp = px[ip1m] - 2.f * px[ip1] + px[ip1p];
        float d4y = d2ym - 2.f * d2y + d2yp;
        float d4x = d2xm - 2.f * d2x + d2xp;

        float ny = fminf(fmaxf(y + STEPSZ * (ALPHA * d2y - BETA * d4y + f0), 0.f), (float)(H - 1));
        float nx = fminf(fmaxf(x + STEPSZ * (ALPHA * d2x - BETA * d4x + f1), 0.f), (float)(W - 1));

        float w0, w1;
        bilin2(gw, ny, nx, w0, w1);
        float d2w = wd[im1] - 2.f * wd[i] + wd[ip1];
        float nw = fminf(fmaxf(wd[i] + STEPSZ * (ALPHA * d2w + (w0 + w1)), 0.f), DMAX);

        qy[i] = ny; qx[i] = nx; qw[i] = nw;
        __syncthreads();          // writes to q visible; no WAR (distinct buffers)
        float* t;
        t = py; py = qy; qy = t;
        t = px; px = qx; qx = t;
        t = wd; wd = qw; qw = t;
    }

    g_nodes[b * NPTS + i] = make_float4(py[i], px[i], wd[i], 0.f);
}

// ---------------- render distance map + per-block squared-error partials ----
// grid (HW/256, B), 256 threads; one pixel per thread.
// float4 node records (1 LDS.128/node), sqrt.approx, 4 min-accumulators.
__global__ void render_loss(const float* __restrict__ pred) {
    __shared__ float4 nd[NPTS];
    __shared__ float red[256];
    const int tid = threadIdx.x;
    const int b = blockIdx.y;

    nd[tid] = g_nodes[b * NPTS + tid];
    __syncthreads();

    const int pix = blockIdx.x * 256 + tid;
    const float yy = (float)(pix >> 8);
    const float xx = (float)(pix & 255);

    float b0 = 3.0e38f, b1 = 3.0e38f, b2 = 3.0e38f, b3 = 3.0e38f;
    #pragma unroll 4
    for (int n = 0; n < NPTS; n += 4) {
        float4 n0 = nd[n+0], n1 = nd[n+1], n2 = nd[n+2], n3 = nd[n+3];
        float dy0 = yy - n0.x, dx0 = xx - n0.y;
        float dy1 = yy - n1.x, dx1 = xx - n1.y;
        float dy2 = yy - n2.x, dx2 = xx - n2.y;
        float dy3 = yy - n3.x, dx3 = xx - n3.y;
        float q0 = fmaf(dy0, dy0, dx0 * dx0);
        float q1 = fmaf(dy1, dy1, dx1 * dx1);
        float q2 = fmaf(dy2, dy2, dx2 * dx2);
        float q3 = fmaf(dy3, dy3, dx3 * dx3);
        b0 = fminf(b0, sqrt_approx(q0) - n0.z);
        b1 = fminf(b1, sqrt_approx(q1) - n1.z);
        b2 = fminf(b2, sqrt_approx(q2) - n2.z);
        b3 = fminf(b3, sqrt_approx(q3) - n3.z);
    }
    float best = fminf(fminf(b0, b1), fminf(b2, b3));
    float dm = fminf(fmaxf(best, 0.f), DMAX);
    float e = pred[b * HW + pix] - dm;
    red[tid] = e * e;
    __syncthreads();
    #pragma unroll
    for (int s = 128; s > 0; s >>= 1) {
        if (tid < s) red[tid] += red[tid + s];
        __syncthreads();
    }
    if (tid == 0) g_part[b * 256 + blockIdx.x] = red[0];
}

// ---------------- final deterministic reduction ----------------
__global__ void final_reduce(float* __restrict__ out) {
    __shared__ float red[256];
    const int tid = threadIdx.x;
    float s = g_part[tid] + g_part[tid + 256] + g_part[tid + 512] + g_part[tid + 768];
    red[tid] = s;
    __syncthreads();
    #pragma unroll
    for (int k = 128; k > 0; k >>= 1) {
        if (tid < k) red[tid] += red[tid + k];
        __syncthreads();
    }
    if (tid == 0) out[0] = red[0] * (1.0f / (float)(B * HW));
}

extern "C" void kernel_launch(void* const* d_in, const int* in_sizes, int n_in,
                              void* d_out, int out_size) {
    const float* pred     = (const float*)d_in[0];  // (4,1,256,256)
    const float* node_pos = (const float*)d_in[1];  // (4,256,2)
    const float* widths   = (const float*)d_in[2];  // (4,256)
    float* out = (float*)d_out;

    conv_pass1<<<B * H, 256>>>(pred);
    conv_pass2<<<B * H, 256>>>();
    snake<<<B, NPTS>>>(node_pos, widths);
    render_loss<<<dim3(HW / 256, B), 256>>>(pred);
    final_reduce<<<1, 256>>>(out);
}

// round 6
// speedup vs baseline: 1.3152x; 1.3152x over previous
#include <cuda_runtime.h>
#include <math.h>

// Problem constants (fixed by setup_inputs)
#define B 4
#define H 256
#define W 256
#define NPTS 256
#define HW (H*W)
#define NSTEPS 50
#define STEPSZ 0.1f
#define ALPHA 0.01f
#define BETA 0.005f
#define DMAX 15.0f
#define EXTGRADFAC 10.0f
// filter: stdev=2 -> r=6 -> 13 taps

// ---------------- device scratch (static allocation: allowed) ----------------
__device__ float4 g_h[B*HW];       // packed {conv_x(p,g), conv_x(p,dg), conv_x(|p|,g), conv_x(|p|,dg)}
__device__ float2 g_gimg [B*HW];   // interleaved {fy,fx} per pixel
__device__ float2 g_gimgW[B*HW];
__device__ float4 g_nodes[B*NPTS]; // {y, x, w, pad}
__device__ float  g_part[1024];
__device__ int    g_cnt = 0;       // last-block counter (self-resetting)

__device__ __forceinline__ float sqrt_approx(float q) {
    float r;
    asm("sqrt.approx.f32 %0, %1;" : "=f"(r) : "f"(q));
    return r;   // exact 0 at q == 0
}

// 13-tap Gaussian / derivative-of-Gaussian filter into shared mem.
// Matches the numpy float32 recipe: g = exp(-x^2/8); g /= sum(g); dg = -x/4 * g.
__device__ __forceinline__ void make_filter(float* g, float* dg, int tid) {
    if (tid < 13) {
        float xv = (float)(tid - 6);
        g[tid] = expf(-xv * xv * 0.125f);
    }
    __syncthreads();
    if (tid == 0) {
        float s = 0.f;
        #pragma unroll
        for (int i = 0; i < 13; i++) s += g[i];
        #pragma unroll
        for (int i = 0; i < 13; i++) {
            g[i]  = g[i] / s;
            dg[i] = -(float)(i - 6) * 0.25f * g[i];
        }
    }
    __syncthreads();
}

// ---------------- pass 1: horizontal separable conv ----------------
// One block per image row (B*H blocks, 256 threads). Packed float4 output.
__global__ void conv_pass1(const float* __restrict__ pred) {
    __shared__ float g[13], dg[13];
    __shared__ float spd[W + 12], sab[W + 12];
    const int tid = threadIdx.x;
    const int row = blockIdx.x;          // b*H + y

    if (tid < 13) {
        float xv = (float)(tid - 6);
        g[tid] = expf(-xv * xv * 0.125f);
    }
    float v = pred[row * W + tid];
    spd[tid + 6] = v;
    sab[tid + 6] = fabsf(v);
    if (tid < 6) {
        spd[tid] = 0.f; sab[tid] = 0.f;
        spd[W + 6 + tid] = 0.f; sab[W + 6 + tid] = 0.f;
    }
    __syncthreads();
    if (tid == 0) {
        float s = 0.f;
        #pragma unroll
        for (int i = 0; i < 13; i++) s += g[i];
        #pragma unroll
        for (int i = 0; i < 13; i++) {
            g[i]  = g[i] / s;
            dg[i] = -(float)(i - 6) * 0.25f * g[i];
        }
    }
    __syncthreads();

    float ag = 0.f, adg = 0.f, bg = 0.f, bdg = 0.f;
    #pragma unroll
    for (int j = 0; j < 13; j++) {
        float p = spd[tid + j];
        float a = sab[tid + j];
        ag  = fmaf(p, g[j],  ag);
        adg = fmaf(p, dg[j], adg);
        bg  = fmaf(a, g[j],  bg);
        bdg = fmaf(a, dg[j], bdg);
    }
    g_h[row * W + tid] = make_float4(ag, adg, bg, bdg);
}

// ---------------- pass 2: vertical separable conv + scale ----------------
// One block per image row; one LDG.128 per tap. Writes interleaved float2.
__global__ void conv_pass2() {
    __shared__ float g[13], dg[13];
    const int tid = threadIdx.x;
    const int row = blockIdx.x;          // b*H + y
    make_filter(g, dg, tid);

    const int b = row >> 8;
    const int y = row & 255;
    float o0 = 0.f, o1 = 0.f, o2 = 0.f, o3 = 0.f;
    #pragma unroll
    for (int i = 0; i < 13; i++) {
        int yy = y + i - 6;
        if (yy < 0 || yy >= H) continue;
        float4 h = __ldg(&g_h[(b * H + yy) * W + tid]);
        o0 = fmaf(h.x, dg[i], o0);   // fy channel of gimg
        o1 = fmaf(h.y, g[i],  o1);   // fx channel of gimg
        o2 = fmaf(h.z, dg[i], o2);   // fy channel of gimgW
        o3 = fmaf(h.w, g[i],  o3);   // fx channel of gimgW
    }
    const int base = b * HW + y * W + tid;
    g_gimg [base] = make_float2(o0 * EXTGRADFAC, o1 * EXTGRADFAC);
    g_gimgW[base] = make_float2(o2 * EXTGRADFAC, o3 * EXTGRADFAC);
}

// ---------------- bilinear samplers ----------------
__device__ __forceinline__ void bilin2(const float2* __restrict__ img,
                                       float y, float x, float& r0, float& r1) {
    y = fminf(fmaxf(y, 0.f), 254.999f);
    x = fminf(fmaxf(x, 0.f), 254.999f);
    float fy = floorf(y), fx = floorf(x);
    int y0 = (int)fy, x0 = (int)fx;
    float ty = y - fy, tx = x - fx;
    float w00 = (1.f - ty) * (1.f - tx);
    float w01 = (1.f - ty) * tx;
    float w10 = ty * (1.f - tx);
    float w11 = ty * tx;
    int i = y0 * W + x0;
    float2 v00 = __ldg(img + i),     v01 = __ldg(img + i + 1);
    float2 v10 = __ldg(img + i + W), v11 = __ldg(img + i + W + 1);
    r0 = v00.x * w00 + v01.x * w01 + v10.x * w10 + v11.x * w11;
    r1 = v00.y * w00 + v01.y * w01 + v10.y * w10 + v11.y * w11;
}

// Sample both images at the same point: 8 concurrent LDG.64, shared index math.
__device__ __forceinline__ void bilin2_pair(const float2* __restrict__ ga,
                                            const float2* __restrict__ gb,
                                            float y, float x,
                                            float& a0, float& a1,
                                            float& b0, float& b1) {
    y = fminf(fmaxf(y, 0.f), 254.999f);
    x = fminf(fmaxf(x, 0.f), 254.999f);
    float fy = floorf(y), fx = floorf(x);
    int y0 = (int)fy, x0 = (int)fx;
    float ty = y - fy, tx = x - fx;
    float w00 = (1.f - ty) * (1.f - tx);
    float w01 = (1.f - ty) * tx;
    float w10 = ty * (1.f - tx);
    float w11 = ty * tx;
    int i = y0 * W + x0;
    float2 p00 = __ldg(ga + i),     p01 = __ldg(ga + i + 1);
    float2 p10 = __ldg(ga + i + W), p11 = __ldg(ga + i + W + 1);
    float2 q00 = __ldg(gb + i),     q01 = __ldg(gb + i + 1);
    float2 q10 = __ldg(gb + i + W), q11 = __ldg(gb + i + W + 1);
    a0 = p00.x * w00 + p01.x * w01 + p10.x * w10 + p11.x * w11;
    a1 = p00.y * w00 + p01.y * w01 + p10.y * w10 + p11.y * w11;
    b0 = q00.x * w00 + q01.x * w01 + q10.x * w10 + q11.x * w11;
    b1 = q00.y * w00 + q01.y * w01 + q10.y * w10 + q11.y * w11;
}

// ---------------- snake optimization: 4 blocks, 256 threads ----------------
// Ping-pong buffers, ONE barrier per step, software-pipelined gathers:
// the gimg sample for step s+1 is issued together with the gimgW sample of
// step s (both at the freshly-updated position) -> one gather latency per
// step; after step 0 the gathers are mostly L1 hits (positions drift slowly).
__global__ void snake(const float* __restrict__ node_pos,
                      const float* __restrict__ widths) {
    __shared__ float pyA[NPTS], pxA[NPTS], wdA[NPTS];
    __shared__ float pyB[NPTS], pxB[NPTS], wdB[NPTS];
    const int i = threadIdx.x;
    const int b = blockIdx.x;
    const float2* gi = g_gimg  + b * HW;
    const float2* gw = g_gimgW + b * HW;

    float y = node_pos[(b * NPTS + i) * 2 + 0];
    float x = node_pos[(b * NPTS + i) * 2 + 1];
    float wcur = widths[b * NPTS + i];
    pyA[i] = y; pxA[i] = x; wdA[i] = wcur;

    // prefetch force for step 0 (overlaps with the barrier)
    float f0, f1;
    bilin2(gi, y, x, f0, f1);
    __syncthreads();

    // clamped neighbor indices (edge replication, matching jnp concat stencil)
    const int im1 = (i == 0) ? 0 : i - 1;
    const int ip1 = (i == NPTS - 1) ? NPTS - 1 : i + 1;
    const int im1m = (im1 == 0) ? 0 : im1 - 1;
    const int im1p = (im1 == NPTS - 1) ? NPTS - 1 : im1 + 1;
    const int ip1m = (ip1 == 0) ? 0 : ip1 - 1;
    const int ip1p = (ip1 == NPTS - 1) ? NPTS - 1 : ip1 + 1;

    float *py = pyA, *px = pxA, *wd = wdA;
    float *qy = pyB, *qx = pxB, *qw = wdB;

    for (int step = 0; step < NSTEPS; step++) {
        // d2 at i, im1, ip1 evaluated directly (exact nested-_d2 semantics)
        float pm1y = py[im1], pp1y = py[ip1];
        float pm1x = px[im1], pp1x = px[ip1];
        float d2y  = pm1y - 2.f * y + pp1y;
        float d2x  = pm1x - 2.f * x + pp1x;
        float d2ym = py[im1m] - 2.f * pm1y + py[im1p];
        float d2xm = px[im1m] - 2.f * pm1x + px[im1p];
        float d2yp = py[ip1m] - 2.f * pp1y + py[ip1p];
        float d2xp = px[ip1m] - 2.f * pp1x + px[ip1p];
        float d4y = d2ym - 2.f * d2y + d2yp;
        float d4x = d2xm - 2.f * d2x + d2xp;

        float ny = fminf(fmaxf(y + STEPSZ * (ALPHA * d2y - BETA * d4y + f0), 0.f), (float)(H - 1));
        float nx = fminf(fmaxf(x + STEPSZ * (ALPHA * d2x - BETA * d4x + f1), 0.f), (float)(W - 1));

        // both gathers at the updated position: width force for THIS step and
        // snake force for the NEXT step, issued concurrently
        float w0, w1, nf0, nf1;
        bilin2_pair(gi, gw, ny, nx, nf0, nf1, w0, w1);

        float d2w = wd[im1] - 2.f * wcur + wd[ip1];
        float nw = fminf(fmaxf(wcur + STEPSZ * (ALPHA * d2w + (w0 + w1)), 0.f), DMAX);

        qy[i] = ny; qx[i] = nx; qw[i] = nw;
        __syncthreads();          // publishes q; no WAR (distinct buffers)
        float* t;
        t = py; py = qy; qy = t;
        t = px; px = qx; qx = t;
        t = wd; wd = qw; qw = t;
        y = ny; x = nx; wcur = nw; f0 = nf0; f1 = nf1;
    }

    g_nodes[b * NPTS + i] = make_float4(y, x, wcur, 0.f);
}

// ---------------- render + loss, tile-culled ----------------
// Grid (16, 16, B): one 16x16 pixel tile per block, 256 threads.
// A node can only influence the (DMAX-clipped) distance of a tile pixel if
// dist(pixel, node) < DMAX + w; culling against the tile center with radius
// margin 7.5*sqrt(2)=10.607 (+1.0 safety) keeps ~10-20 of 256 nodes. Any
// excluded node satisfies d - w >= DMAX for every tile pixel, so it cannot
// change clip(min, 0, DMAX). fminf over the compacted list is
// order-independent (finite floats). Last block does the final reduction.
__global__ void render_loss(const float* __restrict__ pred,
                            float* __restrict__ out) {
    __shared__ float4 kept[NPTS];
    __shared__ int scnt;
    __shared__ float wsum[8];
    __shared__ int slast;
    const int tid = threadIdx.x;
    const int b = blockIdx.z;
    const int tX = blockIdx.x, tY = blockIdx.y;

    const int pyi = tY * 16 + (tid >> 4);
    const int pxi = tX * 16 + (tid & 15);
    float pv = __ldg(&pred[b * HW + pyi * W + pxi]);  // prefetch, overlaps cull

    if (tid == 0) scnt = 0;
    __syncthreads();

    // cull: one node per thread
    {
        float4 n = __ldg(&g_nodes[b * NPTS + tid]);
        const float cy = tY * 16 + 7.5f, cx = tX * 16 + 7.5f;
        float dy = cy - n.x, dx = cx - n.y;
        float d2c = fmaf(dy, dy, dx * dx);
        float thr = DMAX + n.z + 11.62f;
        if (d2c < thr * thr) {
            int k = atomicAdd(&scnt, 1);
            kept[k] = n;
        }
    }
    __syncthreads();
    const int m = scnt;

    const float yy = (float)pyi;
    const float xx = (float)pxi;

    float b0 = 3.0e38f, b1 = 3.0e38f;
    int k = 0;
    for (; k + 2 <= m; k += 2) {
        float4 n0 = kept[k], n1 = kept[k + 1];
        float dy0 = yy - n0.x, dx0 = xx - n0.y;
        float dy1 = yy - n1.x, dx1 = xx - n1.y;
        float q0 = fmaf(dy0, dy0, dx0 * dx0);
        float q1 = fmaf(dy1, dy1, dx1 * dx1);
        b0 = fminf(b0, sqrt_approx(q0) - n0.z);
        b1 = fminf(b1, sqrt_approx(q1) - n1.z);
    }
    if (k < m) {
        float4 n0 = kept[k];
        float dy0 = yy - n0.x, dx0 = xx - n0.y;
        float q0 = fmaf(dy0, dy0, dx0 * dx0);
        b0 = fminf(b0, sqrt_approx(q0) - n0.z);
    }
    float best = fminf(b0, b1);
    float dm = fminf(fmaxf(best, 0.f), DMAX);
    float e = pv - dm;
    float v = e * e;

    // intra-block reduction (warp shuffle + shared)
    #pragma unroll
    for (int s = 16; s > 0; s >>= 1)
        v += __shfl_down_sync(0xFFFFFFFFu, v, s);
    if ((tid & 31) == 0) wsum[tid >> 5] = v;
    __syncthreads();
    if (tid == 0) {
        float s = 0.f;
        #pragma unroll
        for (int j = 0; j < 8; j++) s += wsum[j];
        g_part[b * 256 + tY * 16 + tX] = s;
        __threadfence();
        int t = atomicAdd(&g_cnt, 1);
        slast = (t == 16 * 16 * B - 1);
    }
    __syncthreads();

    // last block: final deterministic reduction over all 1024 partials
    if (slast) {
        float s = g_part[tid] + g_part[tid + 256] + g_part[tid + 512] + g_part[tid + 768];
        #pragma unroll
        for (int sft = 16; sft > 0; sft >>= 1)
            s += __shfl_down_sync(0xFFFFFFFFu, s, sft);
        if ((tid & 31) == 0) wsum[tid >> 5] = s;
        __syncthreads();
        if (tid == 0) {
            float tot = 0.f;
            #pragma unroll
            for (int j = 0; j < 8; j++) tot += wsum[j];
            out[0] = tot * (1.0f / (float)(B * HW));
            g_cnt = 0;   // reset for next graph replay
        }
    }
}

extern "C" void kernel_launch(void* const* d_in, const int* in_sizes, int n_in,
                              void* d_out, int out_size) {
    const float* pred     = (const float*)d_in[0];  // (4,1,256,256)
    const float* node_pos = (const float*)d_in[1];  // (4,256,2)
    const float* widths   = (const float*)d_in[2];  // (4,256)
    float* out = (float*)d_out;

    conv_pass1<<<B * H, 256>>>(pred);
    conv_pass2<<<B * H, 256>>>();
    snake<<<B, NPTS>>>(node_pos, widths);
    render_loss<<<dim3(16, 16, B), 256>>>(pred, out);
}